// round 4
// baseline (speedup 1.0000x reference)
#include <cuda_runtime.h>

#define HWC   65536   // H*W = 256*256
#define WDIM  256
#define NKPT  68
#define OFF_SCALE 6.0f
#define MAXB  256

// Per-batch transform: R (9, row-major, scaled by sd2/sd1) then T (3). 48B rows, 16B aligned.
__device__ __align__(16) float g_RT[MAXB][12];

// ---------------------------------------------------------------------------
// 3x3 inverse via adjugate
// ---------------------------------------------------------------------------
__device__ __forceinline__ void inv3(const float M[9], float Inv[9]) {
    float a = M[0], b = M[1], c = M[2];
    float d = M[3], e = M[4], f = M[5];
    float g = M[6], h = M[7], i = M[8];
    float c0 = e * i - f * h;
    float c3 = f * g - d * i;
    float c6 = d * h - e * g;
    float det = a * c0 + b * c3 + c * c6;
    float inv_det = 1.0f / det;
    Inv[0] = c0 * inv_det;
    Inv[1] = (c * h - b * i) * inv_det;
    Inv[2] = (b * f - c * e) * inv_det;
    Inv[3] = c3 * inv_det;
    Inv[4] = (a * i - c * g) * inv_det;
    Inv[5] = (c * d - a * f) * inv_det;
    Inv[6] = c6 * inv_det;
    Inv[7] = (b * g - a * h) * inv_det;
    Inv[8] = (a * e - b * d) * inv_det;
}

__device__ __forceinline__ float warpSum(float v) {
    #pragma unroll
    for (int o = 16; o > 0; o >>= 1) v += __shfl_xor_sync(0xffffffffu, v, o);
    return v;
}

// ---------------------------------------------------------------------------
// Kernel 1: one WARP per batch. Shuffle reductions, no block barriers.
// Gather keypoints, similarity-normalized cross-covariance H,
// R = polar(H^T) via scaled Newton iteration (== V U^T from SVD).
// ---------------------------------------------------------------------------
__global__ void __launch_bounds__(1024) prep_kernel(
        const float* __restrict__ Off,
        const float* __restrict__ Pos,
        const float* __restrict__ mean,
        const int*   __restrict__ uv,
        int nb) {
    const int lane = threadIdx.x & 31;
    const int b    = (blockIdx.x * blockDim.x + threadIdx.x) >> 5;
    if (b >= nb) return;

    // --- detect int32 vs int64 uv_kpt (values in [0,256)) ---
    int odd = 0;
    for (int i = lane; i < NKPT; i += 32) odd |= uv[2 * i + 1];
    const bool is32 = __ballot_sync(0xffffffffu, odd != 0) != 0u;

    // --- gather: each lane holds up to 3 keypoints (lane, lane+32, lane+64) ---
    const float* ob = Off + (size_t)b * 3 * HWC;
    const float* pb = Pos + (size_t)b * 3 * HWC;
    float sv[3][3], dv[3][3];
    bool  valid[3];
    #pragma unroll
    for (int s = 0; s < 3; s++) {
        const int k = lane + 32 * s;
        valid[s] = (k < NKPT);
        int u = 0, v = 0;
        if (valid[s]) {
            if (is32) { u = uv[2 * k];     v = uv[2 * k + 1]; }
            else      { u = uv[4 * k];     v = uv[4 * k + 2]; }
        }
        const int p = u * WDIM + v;
        #pragma unroll
        for (int c = 0; c < 3; c++) {
            sv[s][c] = valid[s] ? fmaf(ob[c * HWC + p], OFF_SCALE, mean[c * HWC + p]) : 0.f;
            dv[s][c] = valid[s] ? pb[c * HWC + p] : 0.f;
        }
    }

    // keypoint 33 = slot 1, lane 1
    float cs[3], cd[3];
    #pragma unroll
    for (int c = 0; c < 3; c++) {
        cs[c] = __shfl_sync(0xffffffffu, sv[1][c], 1);
        cd[c] = __shfl_sync(0xffffffffu, dv[1][c], 1);
    }

    // local partials
    float n1 = 0.f, n2 = 0.f;
    float ms[3] = {0.f, 0.f, 0.f}, md[3] = {0.f, 0.f, 0.f};
    float SDl[9] = {0.f};
    #pragma unroll
    for (int s = 0; s < 3; s++) {
        if (valid[s]) {
            float dx = sv[s][0] - cs[0], dy = sv[s][1] - cs[1], dz = sv[s][2] - cs[2];
            n1 += sqrtf(dx * dx + dy * dy + dz * dz);
            dx = dv[s][0] - cd[0]; dy = dv[s][1] - cd[1]; dz = dv[s][2] - cd[2];
            n2 += sqrtf(dx * dx + dy * dy + dz * dz);
            #pragma unroll
            for (int c = 0; c < 3; c++) { ms[c] += sv[s][c]; md[c] += dv[s][c]; }
            #pragma unroll
            for (int i = 0; i < 3; i++)
                #pragma unroll
                for (int j = 0; j < 3; j++)
                    SDl[i * 3 + j] += sv[s][i] * dv[s][j];
        }
    }

    const float sd1 = warpSum(n1);
    const float sd2 = warpSum(n2);
    float ssum[3], dsum[3], SD[9];
    #pragma unroll
    for (int c = 0; c < 3; c++) ssum[c] = warpSum(ms[c]);
    #pragma unroll
    for (int c = 0; c < 3; c++) dsum[c] = warpSum(md[c]);
    #pragma unroll
    for (int k = 0; k < 9; k++) SD[k] = warpSum(SDl[k]);

    if (lane == 0) {
        const float ratio = sd2 / sd1;
        const float invn  = 1.0f / (float)NKPT;
        // X = H^T where H[i][j] = ratio * (SD[i][j] - ssum[i]*dsum[j]/n)
        float X[9];
        #pragma unroll
        for (int i = 0; i < 3; i++)
            #pragma unroll
            for (int j = 0; j < 3; j++)
                X[j * 3 + i] = ratio * (SD[i * 3 + j] - ssum[i] * dsum[j] * invn);

        // Scaled Newton polar iteration -> orthogonal factor V U^T
        #pragma unroll 1
        for (int it = 0; it < 10; it++) {
            float Xi[9];
            inv3(X, Xi);
            float nx = 0.f, ni = 0.f;
            #pragma unroll
            for (int k = 0; k < 9; k++) { nx += X[k] * X[k]; ni += Xi[k] * Xi[k]; }
            float z  = sqrtf(sqrtf(ni / nx));
            float zh = 0.5f * z;
            float zi = 0.5f / z;
            float Y[9];
            #pragma unroll
            for (int i = 0; i < 3; i++)
                #pragma unroll
                for (int j = 0; j < 3; j++)
                    Y[i * 3 + j] = zh * X[i * 3 + j] + zi * Xi[j * 3 + i];
            #pragma unroll
            for (int k = 0; k < 9; k++) X[k] = Y[k];
        }

        float Am[3], Bm[3];
        #pragma unroll
        for (int c = 0; c < 3; c++) {
            Am[c] = ratio * ssum[c] * invn;
            Bm[c] = dsum[c] * invn;
        }
        #pragma unroll
        for (int k = 0; k < 9; k++) g_RT[b][k] = ratio * X[k];
        #pragma unroll
        for (int j = 0; j < 3; j++)
            g_RT[b][9 + j] = Bm[j] -
                (Am[0] * X[j * 3 + 0] + Am[1] * X[j * 3 + 1] + Am[2] * X[j * 3 + 2]);
    }
}

// ---------------------------------------------------------------------------
// Kernel 2: streaming transform.
// out[b,j,p] = sum_i Rs[j,i]*(Off[b,i,p]*6+mean[i,p]) + T[j]
// float4 vectorized; streaming hints on the read-once/write-once streams so
// mean (0.77 MB) stays L2-resident across all batches.
// ---------------------------------------------------------------------------
__global__ void __launch_bounds__(256) transform_kernel(
        const float* __restrict__ Off,
        const float* __restrict__ mean,
        float* __restrict__ out) {
    const int b = blockIdx.y;
    const int p = blockIdx.x * blockDim.x + threadIdx.x;  // float4 index
    const int Q = HWC / 4;

    const float4* o  = (const float4*)(Off + (size_t)b * 3 * HWC);
    const float4* m  = (const float4*)mean;
    float4*       ob = (float4*)(out + (size_t)b * 3 * HWC);

    float4 a0 = __ldcs(&o[p]);
    float4 a1 = __ldcs(&o[p + Q]);
    float4 a2 = __ldcs(&o[p + 2 * Q]);
    float4 m0 = __ldg(&m[p]);
    float4 m1 = __ldg(&m[p + Q]);
    float4 m2 = __ldg(&m[p + 2 * Q]);

    const float4* rt4 = (const float4*)(&g_RT[b][0]);
    float4 RA = rt4[0];   // r00 r01 r02 r10
    float4 RB = rt4[1];   // r11 r12 r20 r21
    float4 RC = rt4[2];   // r22 t0  t1  t2
    const float r00 = RA.x, r01 = RA.y, r02 = RA.z;
    const float r10 = RA.w, r11 = RB.x, r12 = RB.y;
    const float r20 = RB.z, r21 = RB.w, r22 = RC.x;
    const float t0  = RC.y, t1  = RC.z, t2  = RC.w;

    float4 y0, y1, y2;
#define COMP(f)                                                         \
    {                                                                   \
        float c0 = fmaf(a0.f, OFF_SCALE, m0.f);                         \
        float c1 = fmaf(a1.f, OFF_SCALE, m1.f);                         \
        float c2 = fmaf(a2.f, OFF_SCALE, m2.f);                         \
        y0.f = fmaf(r00, c0, fmaf(r01, c1, fmaf(r02, c2, t0)));         \
        y1.f = fmaf(r10, c0, fmaf(r11, c1, fmaf(r12, c2, t1)));         \
        y2.f = fmaf(r20, c0, fmaf(r21, c1, fmaf(r22, c2, t2)));         \
    }
    COMP(x) COMP(y) COMP(z) COMP(w)
#undef COMP

    __stcs(&ob[p],         y0);
    __stcs(&ob[p + Q],     y1);
    __stcs(&ob[p + 2 * Q], y2);
}

extern "C" void kernel_launch(void* const* d_in, const int* in_sizes, int n_in,
                              void* d_out, int out_size) {
    const float* Off  = (const float*)d_in[0];
    const float* Pos  = (const float*)d_in[1];
    const float* mean = (const float*)d_in[2];
    const int*   uv   = (const int*)d_in[3];

    int nb = in_sizes[0] / (3 * HWC);
    if (nb > MAXB) nb = MAXB;

    // prep: one warp per batch, 32 warps per CTA
    prep_kernel<<<(nb + 31) / 32, 1024>>>(Off, Pos, mean, uv, nb);

    dim3 grid(HWC / 4 / 256, nb);   // (64, nb)
    transform_kernel<<<grid, 256>>>(Off, mean, (float*)d_out);
}